// round 11
// baseline (speedup 1.0000x reference)
#include <cuda_runtime.h>
#include <cuda_bf16.h>
#include <cstdint>

#define N_NODES 100000
#define N_EDGES 1600000
#define D_IN    128
#define D_OUT   64

// ---------------------------------------------------------------------------
// Scratch (no allocation allowed in kernel_launch)
// ---------------------------------------------------------------------------
__device__ float g_xj[(size_t)N_NODES * D_OUT];
__device__ float g_a1[N_NODES];
__device__ float g_a2[N_NODES];
__device__ int   g_idx_is_i64;          // 1 if edge_index is int64, 0 if int32
// Transposed combined weights, bf16 hi/lo split: [n=128][k=128]
__device__ uint4 g_Wthi4[128 * 128 * 2 / 16];
__device__ uint4 g_Wtlo4[128 * 128 * 2 / 16];
// CSR binning scratch
__device__ int g_cnt[N_NODES];
__device__ int g_off[N_NODES + 1];
__device__ int g_cur[N_NODES];
__device__ int g_edst[N_EDGES];

// ---------------------------------------------------------------------------
// PTX wrappers
// ---------------------------------------------------------------------------
__device__ __forceinline__ void ldsm_x4(uint32_t* r, uint32_t addr) {
    asm volatile("ldmatrix.sync.aligned.m8n8.x4.shared.b16 {%0,%1,%2,%3}, [%4];"
                 : "=r"(r[0]), "=r"(r[1]), "=r"(r[2]), "=r"(r[3]) : "r"(addr));
}
__device__ __forceinline__ void mma_bf16(float* d, const uint32_t* a, const uint32_t* b) {
    asm volatile("mma.sync.aligned.m16n8k16.row.col.f32.bf16.bf16.f32 "
                 "{%0,%1,%2,%3}, {%4,%5,%6,%7}, {%8,%9}, {%0,%1,%2,%3};"
                 : "+f"(d[0]), "+f"(d[1]), "+f"(d[2]), "+f"(d[3])
                 : "r"(a[0]), "r"(a[1]), "r"(a[2]), "r"(a[3]),
                   "r"(b[0]), "r"(b[1]));
}
__device__ __forceinline__ int load_src(const void* ei, int e, int is64) {
    return is64 ? (int)__ldg(&((const long long*)ei)[e])
                : __ldg(&((const int*)ei)[e]);
}
__device__ __forceinline__ int load_dst(const void* ei, int e, int is64) {
    return is64 ? (int)__ldg(&((const long long*)ei)[N_EDGES + e])
                : __ldg(&((const int*)ei)[N_EDGES + e]);
}

// ---------------------------------------------------------------------------
// Kernel 0 (prep): weight transpose + bf16 hi/lo split, edge-dtype sniff,
// and zero the per-node edge counters.
// ---------------------------------------------------------------------------
__global__ __launch_bounds__(256) void prep_kernel(
    const float* __restrict__ W1, const float* __restrict__ W2,
    const int* __restrict__ ei_words)
{
    const int idx = blockIdx.x * 256 + threadIdx.x;   // 64 blocks -> 16384
    const int n = idx >> 7, k = idx & 127;
    float w = (n < 64) ? W1[k * 64 + n] : W2[k * 64 + (n - 64)];
    __nv_bfloat16 hi = __float2bfloat16(w);
    __nv_bfloat16 lo = __float2bfloat16(w - __bfloat162float(hi));
    ((__nv_bfloat16*)g_Wthi4)[idx] = hi;
    ((__nv_bfloat16*)g_Wtlo4)[idx] = lo;

    for (int i = idx; i < N_NODES; i += 64 * 256) g_cnt[i] = 0;

    if (blockIdx.x == 0 && threadIdx.x == 0) {
        int odd_zero = 1;
        for (int i = 1; i < 32; i += 2)
            if (ei_words[i] != 0) odd_zero = 0;
        g_idx_is_i64 = odd_zero;
    }
}

// ---------------------------------------------------------------------------
// Kernel 1: tensor-core dual GEMM (bf16 hi/lo split) + fused epilogue.
// (unchanged from R10 best)
// ---------------------------------------------------------------------------
#define GROWS 64
#define LDS_STRIDE 136
#define A_TILE (GROWS * LDS_STRIDE)
#define B_TILE (128 * LDS_STRIDE)
#define GEMM_SMEM ((2 * A_TILE + 2 * B_TILE) * 2 + 2 * 128 * 4)

__global__ __launch_bounds__(256) void gemm_kernel(
    const float* __restrict__ x0,
    const float* __restrict__ b1, const float* __restrict__ b2,
    const float* __restrict__ wa1, const float* __restrict__ ba1,
    const float* __restrict__ wa2, const float* __restrict__ ba2,
    float* __restrict__ out)
{
    extern __shared__ char smem[];
    __nv_bfloat16* sAhi = (__nv_bfloat16*)smem;
    __nv_bfloat16* sAlo = sAhi + A_TILE;
    __nv_bfloat16* sBhi = sAlo + A_TILE;
    __nv_bfloat16* sBlo = sBhi + B_TILE;
    float* sBias = (float*)(sBlo + B_TILE);
    float* sWa   = sBias + 128;

    const int tid  = threadIdx.x;
    const int row0 = blockIdx.x * GROWS;

    if (tid < 128) {
        sBias[tid] = (tid < 64) ? b1[tid] : b2[tid - 64];
        sWa[tid]   = (tid < 64) ? wa1[tid] : wa2[tid - 64];
    }
    for (int i = tid; i < 2048; i += 256) {
        int n = i >> 4, k0 = (i & 15) * 8;
        *(uint4*)(sBhi + n * LDS_STRIDE + k0) = g_Wthi4[i];
        *(uint4*)(sBlo + n * LDS_STRIDE + k0) = g_Wtlo4[i];
    }
    for (int i = tid; i < GROWS * (D_IN / 4); i += 256) {
        int r = i >> 5, c = (i & 31) * 4;
        int row = row0 + r;
        float4 v = make_float4(0.f, 0.f, 0.f, 0.f);
        if (row < N_NODES)
            v = *(const float4*)(x0 + (size_t)row * D_IN + c);
        __nv_bfloat162 h01 = __floats2bfloat162_rn(v.x, v.y);
        __nv_bfloat162 h23 = __floats2bfloat162_rn(v.z, v.w);
        float2 f01 = __bfloat1622float2(h01);
        float2 f23 = __bfloat1622float2(h23);
        __nv_bfloat162 l01 = __floats2bfloat162_rn(v.x - f01.x, v.y - f01.y);
        __nv_bfloat162 l23 = __floats2bfloat162_rn(v.z - f23.x, v.w - f23.y);
        __nv_bfloat162* ph = (__nv_bfloat162*)(sAhi + r * LDS_STRIDE + c);
        __nv_bfloat162* pl = (__nv_bfloat162*)(sAlo + r * LDS_STRIDE + c);
        ph[0] = h01; ph[1] = h23;
        pl[0] = l01; pl[1] = l23;
    }
    __syncthreads();

    const int w    = tid >> 5;
    const int lane = tid & 31;
    const int m0   = (w >> 1) * 16;
    const int wn   = w & 1;
    const int n0   = wn * 64;

    const uint32_t aAhi = (uint32_t)__cvta_generic_to_shared(sAhi);
    const uint32_t aAlo = (uint32_t)__cvta_generic_to_shared(sAlo);
    const uint32_t aBhi = (uint32_t)__cvta_generic_to_shared(sBhi);
    const uint32_t aBlo = (uint32_t)__cvta_generic_to_shared(sBlo);

    float acc[8][4];
#pragma unroll
    for (int nt = 0; nt < 8; nt++)
#pragma unroll
        for (int q = 0; q < 4; q++) acc[nt][q] = 0.f;

    const uint32_t a_row = m0 + (lane & 15);
    const uint32_t a_kof = (lane >> 4) * 8;
    const uint32_t b_row = (lane & 7) + ((lane >> 4) << 3);
    const uint32_t b_kof = ((lane >> 3) & 1) * 8;

#pragma unroll
    for (int kk = 0; kk < 8; kk++) {
        const uint32_t k0 = kk * 16;
        uint32_t ahi[4], alo[4];
        {
            uint32_t off = (a_row * LDS_STRIDE + k0 + a_kof) * 2;
            ldsm_x4(ahi, aAhi + off);
            ldsm_x4(alo, aAlo + off);
        }
#pragma unroll
        for (int ntp = 0; ntp < 4; ntp++) {
            uint32_t off = ((n0 + ntp * 16 + b_row) * LDS_STRIDE + k0 + b_kof) * 2;
            uint32_t bhi[4], blo[4];
            ldsm_x4(bhi, aBhi + off);
            ldsm_x4(blo, aBlo + off);
            mma_bf16(acc[ntp * 2 + 0], ahi, bhi + 0);
            mma_bf16(acc[ntp * 2 + 0], ahi, blo + 0);
            mma_bf16(acc[ntp * 2 + 0], alo, bhi + 0);
            mma_bf16(acc[ntp * 2 + 1], ahi, bhi + 2);
            mma_bf16(acc[ntp * 2 + 1], ahi, blo + 2);
            mma_bf16(acc[ntp * 2 + 1], alo, bhi + 2);
        }
    }

    float* basep = wn ? g_xj : out;
    const float ba = __ldg(wn ? ba2 : ba1);
    float p0 = 0.f, p1 = 0.f;
    const int rA = row0 + m0 + (lane >> 2);

#pragma unroll
    for (int nt = 0; nt < 8; nt++) {
        const int cg = n0 + nt * 8 + (lane & 3) * 2;
        const int cs = cg - n0;
        const float bb0 = sBias[cg],  bb1 = sBias[cg + 1];
        const float wv0 = sWa[cg],    wv1 = sWa[cg + 1];
        float v0 = fmaxf(acc[nt][0] + bb0, 0.f);
        float v1 = fmaxf(acc[nt][1] + bb1, 0.f);
        float v2 = fmaxf(acc[nt][2] + bb0, 0.f);
        float v3 = fmaxf(acc[nt][3] + bb1, 0.f);
        if (rA < N_NODES)
            *(float2*)(basep + (size_t)rA * D_OUT + cs) = make_float2(v0, v1);
        if (rA + 8 < N_NODES)
            *(float2*)(basep + (size_t)(rA + 8) * D_OUT + cs) = make_float2(v2, v3);
        p0 += v0 * wv0 + v1 * wv1;
        p1 += v2 * wv0 + v3 * wv1;
    }

    float* ga = wn ? g_a2 : g_a1;
#pragma unroll
    for (int h = 0; h < 2; h++) {
        float s = h ? p1 : p0;
        s += __shfl_xor_sync(0xFFFFFFFFu, s, 1);
        s += __shfl_xor_sync(0xFFFFFFFFu, s, 2);
        const int row = row0 + m0 + h * 8 + (lane >> 2);
        if ((lane & 3) == 0 && row < N_NODES)
            ga[row] = s + ba;
    }
}

// ---------------------------------------------------------------------------
// Kernel 2: count edges per src
// ---------------------------------------------------------------------------
__global__ __launch_bounds__(256) void count_kernel(const void* __restrict__ ei)
{
    const int e = blockIdx.x * 256 + threadIdx.x;   // 6250 blocks, exact
    const int s = load_src(ei, e, g_idx_is_i64);
    atomicAdd(&g_cnt[s], 1);
}

// ---------------------------------------------------------------------------
// Kernel 3: exclusive scan of g_cnt -> g_off (and g_cur). Single 1024-thr block.
// ---------------------------------------------------------------------------
__global__ __launch_bounds__(1024) void scan_kernel()
{
    __shared__ int sh[1024];
    const int t = threadIdx.x;
    const int CHUNK = (N_NODES + 1023) / 1024;       // 98
    const int lo = t * CHUNK;
    const int hi = min(lo + CHUNK, N_NODES);

    int sum = 0;
    for (int i = lo; i < hi; i++) sum += g_cnt[i];
    sh[t] = sum;
    __syncthreads();
#pragma unroll
    for (int off = 1; off < 1024; off <<= 1) {
        int v = (t >= off) ? sh[t - off] : 0;
        __syncthreads();
        if (t >= off) sh[t] += v;
        __syncthreads();
    }
    int run = sh[t] - sum;                            // exclusive base
    for (int i = lo; i < hi; i++) {
        int c = g_cnt[i];
        g_off[i] = run;
        g_cur[i] = run;
        run += c;
    }
    if (t == 1023) g_off[N_NODES] = run;
}

// ---------------------------------------------------------------------------
// Kernel 4: scatter dst indices into CSR order
// ---------------------------------------------------------------------------
__global__ __launch_bounds__(256) void scatter_kernel(const void* __restrict__ ei)
{
    const int e = blockIdx.x * 256 + threadIdx.x;   // 6250 blocks, exact
    const int is64 = g_idx_is_i64;
    const int s = load_src(ei, e, is64);
    const int d = load_dst(ei, e, is64);
    const int pos = atomicAdd(&g_cur[s], 1);
    g_edst[pos] = d;
}

// ---------------------------------------------------------------------------
// Kernel 5: per-node aggregation (no atomics).
// One warp per node; two half-warps process alternating edges (2x MLP),
// next-dst prefetched. acc += sigmoid(a1[n]+a2[d]) * x0_j[d]; out[n] += acc.
// ---------------------------------------------------------------------------
__global__ __launch_bounds__(256) void agg_kernel(float* __restrict__ out)
{
    const int wid  = (blockIdx.x * 256 + threadIdx.x) >> 5;  // node id
    if (wid >= N_NODES) return;
    const int lane = threadIdx.x & 31;
    const int sub  = lane >> 4;
    const int l    = lane & 15;

    const int beg = __ldg(&g_off[wid]);
    const int end = __ldg(&g_off[wid + 1]);
    const float a1s = __ldg(&g_a1[wid]);

    float4 acc = make_float4(0.f, 0.f, 0.f, 0.f);

    int i = beg + sub;
    int d = (i < end) ? __ldg(&g_edst[i]) : 0;
    while (i < end) {
        const int ni = i + 2;
        const int nd = (ni < end) ? __ldg(&g_edst[ni]) : 0;
        const float z = a1s + __ldg(&g_a2[d]);
        const float att = 1.f / (1.f + __expf(-z));
        float4 v = __ldg((const float4*)(g_xj + (size_t)d * D_OUT + l * 4));
        acc.x += att * v.x; acc.y += att * v.y;
        acc.z += att * v.z; acc.w += att * v.w;
        i = ni; d = nd;
    }

    // combine the two half-warps (lane and lane+16 hold same column group)
    acc.x += __shfl_down_sync(0xFFFFFFFFu, acc.x, 16);
    acc.y += __shfl_down_sync(0xFFFFFFFFu, acc.y, 16);
    acc.z += __shfl_down_sync(0xFFFFFFFFu, acc.z, 16);
    acc.w += __shfl_down_sync(0xFFFFFFFFu, acc.w, 16);

    if (sub == 0) {
        float4* p = (float4*)(out + (size_t)wid * D_OUT + l * 4);
        float4 o = *p;                                   // x0_i
        o.x += acc.x; o.y += acc.y; o.z += acc.z; o.w += acc.w;
        *p = o;
    }
}

// ---------------------------------------------------------------------------
extern "C" void kernel_launch(void* const* d_in, const int* in_sizes, int n_in,
                              void* d_out, int out_size)
{
    const float* x0  = (const float*)d_in[0];
    // d_in[1] = x1 (unused)
    const void*  ei  = d_in[2];
    const float* W1  = (const float*)d_in[3];
    const float* b1  = (const float*)d_in[4];
    const float* W2  = (const float*)d_in[5];
    const float* b2  = (const float*)d_in[6];
    const float* wa1 = (const float*)d_in[7];
    const float* ba1 = (const float*)d_in[8];
    const float* wa2 = (const float*)d_in[9];
    const float* ba2 = (const float*)d_in[10];
    float* out = (float*)d_out;

    cudaFuncSetAttribute(gemm_kernel,
                         cudaFuncAttributeMaxDynamicSharedMemorySize, GEMM_SMEM);

    // 0) weight split + dtype sniff + zero counters
    prep_kernel<<<64, 256>>>(W1, W2, (const int*)ei);

    // 1) tensor-core dual GEMM + att scalars (x0_i -> out, x0_j -> g_xj)
    gemm_kernel<<<(N_NODES + GROWS - 1) / GROWS, 256, GEMM_SMEM>>>(
        x0, b1, b2, wa1, ba1, wa2, ba2, out);

    // 2) CSR binning: count -> scan -> scatter
    count_kernel<<<N_EDGES / 256, 256>>>(ei);
    scan_kernel<<<1, 1024>>>();
    scatter_kernel<<<N_EDGES / 256, 256>>>(ei);

    // 3) per-node aggregation (atomic-free), fused with +x0_i
    agg_kernel<<<(N_NODES * 32 + 255) / 256, 256>>>(out);
}

// round 12
// speedup vs baseline: 1.9074x; 1.9074x over previous
#include <cuda_runtime.h>
#include <cuda_bf16.h>
#include <cstdint>

#define N_NODES 100000
#define N_EDGES 1600000
#define D_IN    128
#define D_OUT   64
#define SCAN_NB 98                         // ceil(N_NODES / 1024)

// ---------------------------------------------------------------------------
// Scratch (no allocation allowed in kernel_launch)
// ---------------------------------------------------------------------------
__device__ float g_xj[(size_t)N_NODES * D_OUT];
__device__ float g_a1[N_NODES];
__device__ float g_a2[N_NODES];
__device__ int   g_idx_is_i64;          // 1 if edge_index is int64, 0 if int32
// Transposed combined weights, bf16 hi/lo split: [n=128][k=128]
__device__ uint4 g_Wthi4[128 * 128 * 2 / 16];
__device__ uint4 g_Wtlo4[128 * 128 * 2 / 16];
// CSR binning scratch
__device__ int g_cnt[N_NODES];
__device__ int g_off[N_NODES + 1];
__device__ int g_cur[N_NODES];
__device__ int g_edst[N_EDGES];
__device__ int g_bsum[SCAN_NB];
__device__ int g_boff[SCAN_NB];

// ---------------------------------------------------------------------------
// PTX wrappers
// ---------------------------------------------------------------------------
__device__ __forceinline__ void ldsm_x4(uint32_t* r, uint32_t addr) {
    asm volatile("ldmatrix.sync.aligned.m8n8.x4.shared.b16 {%0,%1,%2,%3}, [%4];"
                 : "=r"(r[0]), "=r"(r[1]), "=r"(r[2]), "=r"(r[3]) : "r"(addr));
}
__device__ __forceinline__ void mma_bf16(float* d, const uint32_t* a, const uint32_t* b) {
    asm volatile("mma.sync.aligned.m16n8k16.row.col.f32.bf16.bf16.f32 "
                 "{%0,%1,%2,%3}, {%4,%5,%6,%7}, {%8,%9}, {%0,%1,%2,%3};"
                 : "+f"(d[0]), "+f"(d[1]), "+f"(d[2]), "+f"(d[3])
                 : "r"(a[0]), "r"(a[1]), "r"(a[2]), "r"(a[3]),
                   "r"(b[0]), "r"(b[1]));
}
__device__ __forceinline__ int load_src(const void* ei, int e, int is64) {
    return is64 ? (int)__ldg(&((const long long*)ei)[e])
                : __ldg(&((const int*)ei)[e]);
}
__device__ __forceinline__ int load_dst(const void* ei, int e, int is64) {
    return is64 ? (int)__ldg(&((const long long*)ei)[N_EDGES + e])
                : __ldg(&((const int*)ei)[N_EDGES + e]);
}

// ---------------------------------------------------------------------------
// Kernel 0 (prep): weight transpose + bf16 hi/lo split, edge-dtype sniff,
// and zero the per-node edge counters.
// ---------------------------------------------------------------------------
__global__ __launch_bounds__(256) void prep_kernel(
    const float* __restrict__ W1, const float* __restrict__ W2,
    const int* __restrict__ ei_words)
{
    const int idx = blockIdx.x * 256 + threadIdx.x;   // 64 blocks -> 16384
    const int n = idx >> 7, k = idx & 127;
    float w = (n < 64) ? W1[k * 64 + n] : W2[k * 64 + (n - 64)];
    __nv_bfloat16 hi = __float2bfloat16(w);
    __nv_bfloat16 lo = __float2bfloat16(w - __bfloat162float(hi));
    ((__nv_bfloat16*)g_Wthi4)[idx] = hi;
    ((__nv_bfloat16*)g_Wtlo4)[idx] = lo;

    for (int i = idx; i < N_NODES; i += 64 * 256) g_cnt[i] = 0;

    if (blockIdx.x == 0 && threadIdx.x == 0) {
        int odd_zero = 1;
        for (int i = 1; i < 32; i += 2)
            if (ei_words[i] != 0) odd_zero = 0;
        g_idx_is_i64 = odd_zero;
    }
}

// ---------------------------------------------------------------------------
// Kernel 1: tensor-core dual GEMM (bf16 hi/lo split) + fused epilogue.
// (unchanged from R10 best)
// ---------------------------------------------------------------------------
#define GROWS 64
#define LDS_STRIDE 136
#define A_TILE (GROWS * LDS_STRIDE)
#define B_TILE (128 * LDS_STRIDE)
#define GEMM_SMEM ((2 * A_TILE + 2 * B_TILE) * 2 + 2 * 128 * 4)

__global__ __launch_bounds__(256) void gemm_kernel(
    const float* __restrict__ x0,
    const float* __restrict__ b1, const float* __restrict__ b2,
    const float* __restrict__ wa1, const float* __restrict__ ba1,
    const float* __restrict__ wa2, const float* __restrict__ ba2,
    float* __restrict__ out)
{
    extern __shared__ char smem[];
    __nv_bfloat16* sAhi = (__nv_bfloat16*)smem;
    __nv_bfloat16* sAlo = sAhi + A_TILE;
    __nv_bfloat16* sBhi = sAlo + A_TILE;
    __nv_bfloat16* sBlo = sBhi + B_TILE;
    float* sBias = (float*)(sBlo + B_TILE);
    float* sWa   = sBias + 128;

    const int tid  = threadIdx.x;
    const int row0 = blockIdx.x * GROWS;

    if (tid < 128) {
        sBias[tid] = (tid < 64) ? b1[tid] : b2[tid - 64];
        sWa[tid]   = (tid < 64) ? wa1[tid] : wa2[tid - 64];
    }
    for (int i = tid; i < 2048; i += 256) {
        int n = i >> 4, k0 = (i & 15) * 8;
        *(uint4*)(sBhi + n * LDS_STRIDE + k0) = g_Wthi4[i];
        *(uint4*)(sBlo + n * LDS_STRIDE + k0) = g_Wtlo4[i];
    }
    for (int i = tid; i < GROWS * (D_IN / 4); i += 256) {
        int r = i >> 5, c = (i & 31) * 4;
        int row = row0 + r;
        float4 v = make_float4(0.f, 0.f, 0.f, 0.f);
        if (row < N_NODES)
            v = *(const float4*)(x0 + (size_t)row * D_IN + c);
        __nv_bfloat162 h01 = __floats2bfloat162_rn(v.x, v.y);
        __nv_bfloat162 h23 = __floats2bfloat162_rn(v.z, v.w);
        float2 f01 = __bfloat1622float2(h01);
        float2 f23 = __bfloat1622float2(h23);
        __nv_bfloat162 l01 = __floats2bfloat162_rn(v.x - f01.x, v.y - f01.y);
        __nv_bfloat162 l23 = __floats2bfloat162_rn(v.z - f23.x, v.w - f23.y);
        __nv_bfloat162* ph = (__nv_bfloat162*)(sAhi + r * LDS_STRIDE + c);
        __nv_bfloat162* pl = (__nv_bfloat162*)(sAlo + r * LDS_STRIDE + c);
        ph[0] = h01; ph[1] = h23;
        pl[0] = l01; pl[1] = l23;
    }
    __syncthreads();

    const int w    = tid >> 5;
    const int lane = tid & 31;
    const int m0   = (w >> 1) * 16;
    const int wn   = w & 1;
    const int n0   = wn * 64;

    const uint32_t aAhi = (uint32_t)__cvta_generic_to_shared(sAhi);
    const uint32_t aAlo = (uint32_t)__cvta_generic_to_shared(sAlo);
    const uint32_t aBhi = (uint32_t)__cvta_generic_to_shared(sBhi);
    const uint32_t aBlo = (uint32_t)__cvta_generic_to_shared(sBlo);

    float acc[8][4];
#pragma unroll
    for (int nt = 0; nt < 8; nt++)
#pragma unroll
        for (int q = 0; q < 4; q++) acc[nt][q] = 0.f;

    const uint32_t a_row = m0 + (lane & 15);
    const uint32_t a_kof = (lane >> 4) * 8;
    const uint32_t b_row = (lane & 7) + ((lane >> 4) << 3);
    const uint32_t b_kof = ((lane >> 3) & 1) * 8;

#pragma unroll
    for (int kk = 0; kk < 8; kk++) {
        const uint32_t k0 = kk * 16;
        uint32_t ahi[4], alo[4];
        {
            uint32_t off = (a_row * LDS_STRIDE + k0 + a_kof) * 2;
            ldsm_x4(ahi, aAhi + off);
            ldsm_x4(alo, aAlo + off);
        }
#pragma unroll
        for (int ntp = 0; ntp < 4; ntp++) {
            uint32_t off = ((n0 + ntp * 16 + b_row) * LDS_STRIDE + k0 + b_kof) * 2;
            uint32_t bhi[4], blo[4];
            ldsm_x4(bhi, aBhi + off);
            ldsm_x4(blo, aBlo + off);
            mma_bf16(acc[ntp * 2 + 0], ahi, bhi + 0);
            mma_bf16(acc[ntp * 2 + 0], ahi, blo + 0);
            mma_bf16(acc[ntp * 2 + 0], alo, bhi + 0);
            mma_bf16(acc[ntp * 2 + 1], ahi, bhi + 2);
            mma_bf16(acc[ntp * 2 + 1], ahi, blo + 2);
            mma_bf16(acc[ntp * 2 + 1], alo, bhi + 2);
        }
    }

    float* basep = wn ? g_xj : out;
    const float ba = __ldg(wn ? ba2 : ba1);
    float p0 = 0.f, p1 = 0.f;
    const int rA = row0 + m0 + (lane >> 2);

#pragma unroll
    for (int nt = 0; nt < 8; nt++) {
        const int cg = n0 + nt * 8 + (lane & 3) * 2;
        const int cs = cg - n0;
        const float bb0 = sBias[cg],  bb1 = sBias[cg + 1];
        const float wv0 = sWa[cg],    wv1 = sWa[cg + 1];
        float v0 = fmaxf(acc[nt][0] + bb0, 0.f);
        float v1 = fmaxf(acc[nt][1] + bb1, 0.f);
        float v2 = fmaxf(acc[nt][2] + bb0, 0.f);
        float v3 = fmaxf(acc[nt][3] + bb1, 0.f);
        if (rA < N_NODES)
            *(float2*)(basep + (size_t)rA * D_OUT + cs) = make_float2(v0, v1);
        if (rA + 8 < N_NODES)
            *(float2*)(basep + (size_t)(rA + 8) * D_OUT + cs) = make_float2(v2, v3);
        p0 += v0 * wv0 + v1 * wv1;
        p1 += v2 * wv0 + v3 * wv1;
    }

    float* ga = wn ? g_a2 : g_a1;
#pragma unroll
    for (int h = 0; h < 2; h++) {
        float s = h ? p1 : p0;
        s += __shfl_xor_sync(0xFFFFFFFFu, s, 1);
        s += __shfl_xor_sync(0xFFFFFFFFu, s, 2);
        const int row = row0 + m0 + h * 8 + (lane >> 2);
        if ((lane & 3) == 0 && row < N_NODES)
            ga[row] = s + ba;
    }
}

// ---------------------------------------------------------------------------
// Kernel 2: count edges per src
// ---------------------------------------------------------------------------
__global__ __launch_bounds__(256) void count_kernel(const void* __restrict__ ei)
{
    const int e = blockIdx.x * 256 + threadIdx.x;   // 6250 blocks, exact
    const int s = load_src(ei, e, g_idx_is_i64);
    atomicAdd(&g_cnt[s], 1);
}

// ---------------------------------------------------------------------------
// Kernels 3a/3b/3c: parallel exclusive scan of g_cnt -> g_off/g_cur.
// 3a: per-block (1024 elems) exclusive scan + block sums
// 3b: scan the 98 block sums (single tiny block)
// 3c: add block prefix, write g_off and g_cur
// ---------------------------------------------------------------------------
__global__ __launch_bounds__(1024) void scan_blocks_kernel()
{
    __shared__ int ws[32];
    const int i    = blockIdx.x * 1024 + threadIdx.x;
    const int lane = threadIdx.x & 31;
    const int wid  = threadIdx.x >> 5;

    const int c = (i < N_NODES) ? g_cnt[i] : 0;
    int v = c;
#pragma unroll
    for (int off = 1; off < 32; off <<= 1) {
        int t = __shfl_up_sync(0xFFFFFFFFu, v, off);
        if (lane >= off) v += t;
    }
    if (lane == 31) ws[wid] = v;
    __syncthreads();
    if (wid == 0) {
        int s = ws[lane];
#pragma unroll
        for (int off = 1; off < 32; off <<= 1) {
            int t = __shfl_up_sync(0xFFFFFFFFu, s, off);
            if (lane >= off) s += t;
        }
        ws[lane] = s;
    }
    __syncthreads();
    const int excl = v - c + (wid > 0 ? ws[wid - 1] : 0);
    if (i < N_NODES) g_off[i] = excl;                // block-local for now
    if (threadIdx.x == 1023) g_bsum[blockIdx.x] = excl + c;
}

__global__ __launch_bounds__(128) void scan_tops_kernel()
{
    __shared__ int sh[SCAN_NB];
    const int t = threadIdx.x;
    if (t < SCAN_NB) sh[t] = g_bsum[t];
    __syncthreads();
    if (t == 0) {                        // 98 elems: serial in smem is ~free
        int run = 0;
        for (int i = 0; i < SCAN_NB; i++) {
            int c = sh[i];
            g_boff[i] = run;
            run += c;
        }
    }
}

__global__ __launch_bounds__(1024) void scan_fix_kernel()
{
    const int i = blockIdx.x * 1024 + threadIdx.x;
    if (i < N_NODES) {
        const int o = g_off[i] + g_boff[blockIdx.x];
        g_off[i] = o;
        g_cur[i] = o;
    }
    if (i == 0) g_off[N_NODES] = N_EDGES;   // all edges counted by construction
}

// ---------------------------------------------------------------------------
// Kernel 4: scatter dst indices into CSR order
// ---------------------------------------------------------------------------
__global__ __launch_bounds__(256) void scatter_kernel(const void* __restrict__ ei)
{
    const int e = blockIdx.x * 256 + threadIdx.x;   // 6250 blocks, exact
    const int is64 = g_idx_is_i64;
    const int s = load_src(ei, e, is64);
    const int d = load_dst(ei, e, is64);
    const int pos = atomicAdd(&g_cur[s], 1);
    g_edst[pos] = d;
}

// ---------------------------------------------------------------------------
// Kernel 5: per-node aggregation (no atomics).
// One warp per node; two half-warps process alternating edges (2x MLP),
// next-dst prefetched. acc += sigmoid(a1[n]+a2[d]) * x0_j[d]; out[n] += acc.
// ---------------------------------------------------------------------------
__global__ __launch_bounds__(256) void agg_kernel(float* __restrict__ out)
{
    const int wid  = (blockIdx.x * 256 + threadIdx.x) >> 5;  // node id
    if (wid >= N_NODES) return;
    const int lane = threadIdx.x & 31;
    const int sub  = lane >> 4;
    const int l    = lane & 15;

    const int beg = __ldg(&g_off[wid]);
    const int end = __ldg(&g_off[wid + 1]);
    const float a1s = __ldg(&g_a1[wid]);

    float4 acc = make_float4(0.f, 0.f, 0.f, 0.f);

    int i = beg + sub;
    int d = (i < end) ? __ldg(&g_edst[i]) : 0;
    while (i < end) {
        const int ni = i + 2;
        const int nd = (ni < end) ? __ldg(&g_edst[ni]) : 0;
        const float z = a1s + __ldg(&g_a2[d]);
        const float att = 1.f / (1.f + __expf(-z));
        float4 v = __ldg((const float4*)(g_xj + (size_t)d * D_OUT + l * 4));
        acc.x += att * v.x; acc.y += att * v.y;
        acc.z += att * v.z; acc.w += att * v.w;
        i = ni; d = nd;
    }

    // combine the two half-warps (lane and lane+16 hold same column group)
    acc.x += __shfl_down_sync(0xFFFFFFFFu, acc.x, 16);
    acc.y += __shfl_down_sync(0xFFFFFFFFu, acc.y, 16);
    acc.z += __shfl_down_sync(0xFFFFFFFFu, acc.z, 16);
    acc.w += __shfl_down_sync(0xFFFFFFFFu, acc.w, 16);

    if (sub == 0) {
        float4* p = (float4*)(out + (size_t)wid * D_OUT + l * 4);
        float4 o = *p;                                   // x0_i
        o.x += acc.x; o.y += acc.y; o.z += acc.z; o.w += acc.w;
        *p = o;
    }
}

// ---------------------------------------------------------------------------
extern "C" void kernel_launch(void* const* d_in, const int* in_sizes, int n_in,
                              void* d_out, int out_size)
{
    const float* x0  = (const float*)d_in[0];
    // d_in[1] = x1 (unused)
    const void*  ei  = d_in[2];
    const float* W1  = (const float*)d_in[3];
    const float* b1  = (const float*)d_in[4];
    const float* W2  = (const float*)d_in[5];
    const float* b2  = (const float*)d_in[6];
    const float* wa1 = (const float*)d_in[7];
    const float* ba1 = (const float*)d_in[8];
    const float* wa2 = (const float*)d_in[9];
    const float* ba2 = (const float*)d_in[10];
    float* out = (float*)d_out;

    cudaFuncSetAttribute(gemm_kernel,
                         cudaFuncAttributeMaxDynamicSharedMemorySize, GEMM_SMEM);

    // 0) weight split + dtype sniff + zero counters
    prep_kernel<<<64, 256>>>(W1, W2, (const int*)ei);

    // 1) tensor-core dual GEMM + att scalars (x0_i -> out, x0_j -> g_xj)
    gemm_kernel<<<(N_NODES + GROWS - 1) / GROWS, 256, GEMM_SMEM>>>(
        x0, b1, b2, wa1, ba1, wa2, ba2, out);

    // 2) CSR binning: count -> parallel scan -> scatter
    count_kernel<<<N_EDGES / 256, 256>>>(ei);
    scan_blocks_kernel<<<SCAN_NB, 1024>>>();
    scan_tops_kernel<<<1, 128>>>();
    scan_fix_kernel<<<SCAN_NB, 1024>>>();
    scatter_kernel<<<N_EDGES / 256, 256>>>(ei);

    // 3) per-node aggregation (atomic-free), fused with +x0_i
    agg_kernel<<<(N_NODES * 32 + 255) / 256, 256>>>(out);
}

// round 13
// speedup vs baseline: 2.0031x; 1.0501x over previous
#include <cuda_runtime.h>
#include <cuda_bf16.h>
#include <cstdint>

#define N_NODES 100000
#define N_EDGES 1600000
#define D_IN    128
#define D_OUT   64
#define SCAN_NB 98                         // ceil(N_NODES / 1024)

// ---------------------------------------------------------------------------
// Scratch (no allocation allowed in kernel_launch)
// ---------------------------------------------------------------------------
__device__ float g_xj[(size_t)N_NODES * D_OUT];
__device__ float g_a1[N_NODES];
__device__ float g_a2[N_NODES];
__device__ int   g_idx_is_i64;          // 1 if edge_index is int64, 0 if int32
// Transposed combined weights, bf16 hi/lo split: [n=128][k=128]
__device__ uint4 g_Wthi4[128 * 128 * 2 / 16];
__device__ uint4 g_Wtlo4[128 * 128 * 2 / 16];
// CSR binning scratch
__device__ int g_cnt[N_NODES];
__device__ int g_off[N_NODES + 1];
__device__ int g_cur[N_NODES];
__device__ int g_edst[N_EDGES];
__device__ int g_bsum[SCAN_NB];
__device__ int g_boff[SCAN_NB];

// ---------------------------------------------------------------------------
// PTX wrappers
// ---------------------------------------------------------------------------
__device__ __forceinline__ void ldsm_x4(uint32_t* r, uint32_t addr) {
    asm volatile("ldmatrix.sync.aligned.m8n8.x4.shared.b16 {%0,%1,%2,%3}, [%4];"
                 : "=r"(r[0]), "=r"(r[1]), "=r"(r[2]), "=r"(r[3]) : "r"(addr));
}
__device__ __forceinline__ void mma_bf16(float* d, const uint32_t* a, const uint32_t* b) {
    asm volatile("mma.sync.aligned.m16n8k16.row.col.f32.bf16.bf16.f32 "
                 "{%0,%1,%2,%3}, {%4,%5,%6,%7}, {%8,%9}, {%0,%1,%2,%3};"
                 : "+f"(d[0]), "+f"(d[1]), "+f"(d[2]), "+f"(d[3])
                 : "r"(a[0]), "r"(a[1]), "r"(a[2]), "r"(a[3]),
                   "r"(b[0]), "r"(b[1]));
}
__device__ __forceinline__ int load_src(const void* ei, int e, int is64) {
    return is64 ? (int)__ldg(&((const long long*)ei)[e])
                : __ldg(&((const int*)ei)[e]);
}
__device__ __forceinline__ int load_dst(const void* ei, int e, int is64) {
    return is64 ? (int)__ldg(&((const long long*)ei)[N_EDGES + e])
                : __ldg(&((const int*)ei)[N_EDGES + e]);
}

// ---------------------------------------------------------------------------
// Kernel 0 (prep): weight transpose + bf16 hi/lo split, edge-dtype sniff,
// and zero the per-node edge counters.
// ---------------------------------------------------------------------------
__global__ __launch_bounds__(256) void prep_kernel(
    const float* __restrict__ W1, const float* __restrict__ W2,
    const int* __restrict__ ei_words)
{
    const int idx = blockIdx.x * 256 + threadIdx.x;   // 64 blocks -> 16384
    const int n = idx >> 7, k = idx & 127;
    float w = (n < 64) ? W1[k * 64 + n] : W2[k * 64 + (n - 64)];
    __nv_bfloat16 hi = __float2bfloat16(w);
    __nv_bfloat16 lo = __float2bfloat16(w - __bfloat162float(hi));
    ((__nv_bfloat16*)g_Wthi4)[idx] = hi;
    ((__nv_bfloat16*)g_Wtlo4)[idx] = lo;

    for (int i = idx; i < N_NODES; i += 64 * 256) g_cnt[i] = 0;

    if (blockIdx.x == 0 && threadIdx.x == 0) {
        int odd_zero = 1;
        for (int i = 1; i < 32; i += 2)
            if (ei_words[i] != 0) odd_zero = 0;
        g_idx_is_i64 = odd_zero;
    }
}

// ---------------------------------------------------------------------------
// Kernel 1: tensor-core dual GEMM (bf16 hi/lo split) + fused epilogue.
// (unchanged from R10/R12 best)
// ---------------------------------------------------------------------------
#define GROWS 64
#define LDS_STRIDE 136
#define A_TILE (GROWS * LDS_STRIDE)
#define B_TILE (128 * LDS_STRIDE)
#define GEMM_SMEM ((2 * A_TILE + 2 * B_TILE) * 2 + 2 * 128 * 4)

__global__ __launch_bounds__(256) void gemm_kernel(
    const float* __restrict__ x0,
    const float* __restrict__ b1, const float* __restrict__ b2,
    const float* __restrict__ wa1, const float* __restrict__ ba1,
    const float* __restrict__ wa2, const float* __restrict__ ba2,
    float* __restrict__ out)
{
    extern __shared__ char smem[];
    __nv_bfloat16* sAhi = (__nv_bfloat16*)smem;
    __nv_bfloat16* sAlo = sAhi + A_TILE;
    __nv_bfloat16* sBhi = sAlo + A_TILE;
    __nv_bfloat16* sBlo = sBhi + B_TILE;
    float* sBias = (float*)(sBlo + B_TILE);
    float* sWa   = sBias + 128;

    const int tid  = threadIdx.x;
    const int row0 = blockIdx.x * GROWS;

    if (tid < 128) {
        sBias[tid] = (tid < 64) ? b1[tid] : b2[tid - 64];
        sWa[tid]   = (tid < 64) ? wa1[tid] : wa2[tid - 64];
    }
    for (int i = tid; i < 2048; i += 256) {
        int n = i >> 4, k0 = (i & 15) * 8;
        *(uint4*)(sBhi + n * LDS_STRIDE + k0) = g_Wthi4[i];
        *(uint4*)(sBlo + n * LDS_STRIDE + k0) = g_Wtlo4[i];
    }
    for (int i = tid; i < GROWS * (D_IN / 4); i += 256) {
        int r = i >> 5, c = (i & 31) * 4;
        int row = row0 + r;
        float4 v = make_float4(0.f, 0.f, 0.f, 0.f);
        if (row < N_NODES)
            v = *(const float4*)(x0 + (size_t)row * D_IN + c);
        __nv_bfloat162 h01 = __floats2bfloat162_rn(v.x, v.y);
        __nv_bfloat162 h23 = __floats2bfloat162_rn(v.z, v.w);
        float2 f01 = __bfloat1622float2(h01);
        float2 f23 = __bfloat1622float2(h23);
        __nv_bfloat162 l01 = __floats2bfloat162_rn(v.x - f01.x, v.y - f01.y);
        __nv_bfloat162 l23 = __floats2bfloat162_rn(v.z - f23.x, v.w - f23.y);
        __nv_bfloat162* ph = (__nv_bfloat162*)(sAhi + r * LDS_STRIDE + c);
        __nv_bfloat162* pl = (__nv_bfloat162*)(sAlo + r * LDS_STRIDE + c);
        ph[0] = h01; ph[1] = h23;
        pl[0] = l01; pl[1] = l23;
    }
    __syncthreads();

    const int w    = tid >> 5;
    const int lane = tid & 31;
    const int m0   = (w >> 1) * 16;
    const int wn   = w & 1;
    const int n0   = wn * 64;

    const uint32_t aAhi = (uint32_t)__cvta_generic_to_shared(sAhi);
    const uint32_t aAlo = (uint32_t)__cvta_generic_to_shared(sAlo);
    const uint32_t aBhi = (uint32_t)__cvta_generic_to_shared(sBhi);
    const uint32_t aBlo = (uint32_t)__cvta_generic_to_shared(sBlo);

    float acc[8][4];
#pragma unroll
    for (int nt = 0; nt < 8; nt++)
#pragma unroll
        for (int q = 0; q < 4; q++) acc[nt][q] = 0.f;

    const uint32_t a_row = m0 + (lane & 15);
    const uint32_t a_kof = (lane >> 4) * 8;
    const uint32_t b_row = (lane & 7) + ((lane >> 4) << 3);
    const uint32_t b_kof = ((lane >> 3) & 1) * 8;

#pragma unroll
    for (int kk = 0; kk < 8; kk++) {
        const uint32_t k0 = kk * 16;
        uint32_t ahi[4], alo[4];
        {
            uint32_t off = (a_row * LDS_STRIDE + k0 + a_kof) * 2;
            ldsm_x4(ahi, aAhi + off);
            ldsm_x4(alo, aAlo + off);
        }
#pragma unroll
        for (int ntp = 0; ntp < 4; ntp++) {
            uint32_t off = ((n0 + ntp * 16 + b_row) * LDS_STRIDE + k0 + b_kof) * 2;
            uint32_t bhi[4], blo[4];
            ldsm_x4(bhi, aBhi + off);
            ldsm_x4(blo, aBlo + off);
            mma_bf16(acc[ntp * 2 + 0], ahi, bhi + 0);
            mma_bf16(acc[ntp * 2 + 0], ahi, blo + 0);
            mma_bf16(acc[ntp * 2 + 0], alo, bhi + 0);
            mma_bf16(acc[ntp * 2 + 1], ahi, bhi + 2);
            mma_bf16(acc[ntp * 2 + 1], ahi, blo + 2);
            mma_bf16(acc[ntp * 2 + 1], alo, bhi + 2);
        }
    }

    float* basep = wn ? g_xj : out;
    const float ba = __ldg(wn ? ba2 : ba1);
    float p0 = 0.f, p1 = 0.f;
    const int rA = row0 + m0 + (lane >> 2);

#pragma unroll
    for (int nt = 0; nt < 8; nt++) {
        const int cg = n0 + nt * 8 + (lane & 3) * 2;
        const int cs = cg - n0;
        const float bb0 = sBias[cg],  bb1 = sBias[cg + 1];
        const float wv0 = sWa[cg],    wv1 = sWa[cg + 1];
        float v0 = fmaxf(acc[nt][0] + bb0, 0.f);
        float v1 = fmaxf(acc[nt][1] + bb1, 0.f);
        float v2 = fmaxf(acc[nt][2] + bb0, 0.f);
        float v3 = fmaxf(acc[nt][3] + bb1, 0.f);
        if (rA < N_NODES)
            *(float2*)(basep + (size_t)rA * D_OUT + cs) = make_float2(v0, v1);
        if (rA + 8 < N_NODES)
            *(float2*)(basep + (size_t)(rA + 8) * D_OUT + cs) = make_float2(v2, v3);
        p0 += v0 * wv0 + v1 * wv1;
        p1 += v2 * wv0 + v3 * wv1;
    }

    float* ga = wn ? g_a2 : g_a1;
#pragma unroll
    for (int h = 0; h < 2; h++) {
        float s = h ? p1 : p0;
        s += __shfl_xor_sync(0xFFFFFFFFu, s, 1);
        s += __shfl_xor_sync(0xFFFFFFFFu, s, 2);
        const int row = row0 + m0 + h * 8 + (lane >> 2);
        if ((lane & 3) == 0 && row < N_NODES)
            ga[row] = s + ba;
    }
}

// ---------------------------------------------------------------------------
// Kernel 2: count edges per src
// ---------------------------------------------------------------------------
__global__ __launch_bounds__(256) void count_kernel(const void* __restrict__ ei)
{
    const int e = blockIdx.x * 256 + threadIdx.x;   // 6250 blocks, exact
    const int s = load_src(ei, e, g_idx_is_i64);
    atomicAdd(&g_cnt[s], 1);
}

// ---------------------------------------------------------------------------
// Kernels 3a/3b/3c: parallel exclusive scan of g_cnt -> g_off/g_cur.
// ---------------------------------------------------------------------------
__global__ __launch_bounds__(1024) void scan_blocks_kernel()
{
    __shared__ int ws[32];
    const int i    = blockIdx.x * 1024 + threadIdx.x;
    const int lane = threadIdx.x & 31;
    const int wid  = threadIdx.x >> 5;

    const int c = (i < N_NODES) ? g_cnt[i] : 0;
    int v = c;
#pragma unroll
    for (int off = 1; off < 32; off <<= 1) {
        int t = __shfl_up_sync(0xFFFFFFFFu, v, off);
        if (lane >= off) v += t;
    }
    if (lane == 31) ws[wid] = v;
    __syncthreads();
    if (wid == 0) {
        int s = ws[lane];
#pragma unroll
        for (int off = 1; off < 32; off <<= 1) {
            int t = __shfl_up_sync(0xFFFFFFFFu, s, off);
            if (lane >= off) s += t;
        }
        ws[lane] = s;
    }
    __syncthreads();
    const int excl = v - c + (wid > 0 ? ws[wid - 1] : 0);
    if (i < N_NODES) g_off[i] = excl;                // block-local for now
    if (threadIdx.x == 1023) g_bsum[blockIdx.x] = excl + c;
}

__global__ __launch_bounds__(128) void scan_tops_kernel()
{
    __shared__ int sh[SCAN_NB];
    const int t = threadIdx.x;
    if (t < SCAN_NB) sh[t] = g_bsum[t];
    __syncthreads();
    if (t == 0) {                        // 98 elems: serial in smem is ~free
        int run = 0;
        for (int i = 0; i < SCAN_NB; i++) {
            int c = sh[i];
            g_boff[i] = run;
            run += c;
        }
    }
}

__global__ __launch_bounds__(1024) void scan_fix_kernel()
{
    const int i = blockIdx.x * 1024 + threadIdx.x;
    if (i < N_NODES) {
        const int o = g_off[i] + g_boff[blockIdx.x];
        g_off[i] = o;
        g_cur[i] = o;
    }
    if (i == 0) g_off[N_NODES] = N_EDGES;   // all edges counted by construction
}

// ---------------------------------------------------------------------------
// Kernel 4: scatter dst indices into CSR order
// ---------------------------------------------------------------------------
__global__ __launch_bounds__(256) void scatter_kernel(const void* __restrict__ ei)
{
    const int e = blockIdx.x * 256 + threadIdx.x;   // 6250 blocks, exact
    const int is64 = g_idx_is_i64;
    const int s = load_src(ei, e, is64);
    const int d = load_dst(ei, e, is64);
    const int pos = atomicAdd(&g_cur[s], 1);
    g_edst[pos] = d;
}

// ---------------------------------------------------------------------------
// Kernel 5: per-node aggregation (no atomics).
// ---------------------------------------------------------------------------
__global__ __launch_bounds__(256) void agg_kernel(float* __restrict__ out)
{
    const int wid  = (blockIdx.x * 256 + threadIdx.x) >> 5;  // node id
    if (wid >= N_NODES) return;
    const int lane = threadIdx.x & 31;
    const int sub  = lane >> 4;
    const int l    = lane & 15;

    const int beg = __ldg(&g_off[wid]);
    const int end = __ldg(&g_off[wid + 1]);
    const float a1s = __ldg(&g_a1[wid]);

    float4 acc = make_float4(0.f, 0.f, 0.f, 0.f);

    int i = beg + sub;
    int d = (i < end) ? __ldg(&g_edst[i]) : 0;
    while (i < end) {
        const int ni = i + 2;
        const int nd = (ni < end) ? __ldg(&g_edst[ni]) : 0;
        const float z = a1s + __ldg(&g_a2[d]);
        const float att = 1.f / (1.f + __expf(-z));
        float4 v = __ldg((const float4*)(g_xj + (size_t)d * D_OUT + l * 4));
        acc.x += att * v.x; acc.y += att * v.y;
        acc.z += att * v.z; acc.w += att * v.w;
        i = ni; d = nd;
    }

    acc.x += __shfl_down_sync(0xFFFFFFFFu, acc.x, 16);
    acc.y += __shfl_down_sync(0xFFFFFFFFu, acc.y, 16);
    acc.z += __shfl_down_sync(0xFFFFFFFFu, acc.z, 16);
    acc.w += __shfl_down_sync(0xFFFFFFFFu, acc.w, 16);

    if (sub == 0) {
        float4* p = (float4*)(out + (size_t)wid * D_OUT + l * 4);
        float4 o = *p;                                   // x0_i
        o.x += acc.x; o.y += acc.y; o.z += acc.z; o.w += acc.w;
        *p = o;
    }
}

// ---------------------------------------------------------------------------
// Launch: fork-join so the CSR build (edge-index only) overlaps the GEMM.
//   main:  prep ─┬─ gemm ──────────────┬─ agg
//   side:        └ count→scan*3→scatter┘
// Stream/events are created per call (kernel_launch runs only for correctness
// + capture, so the small host-side residue is bounded); all ops are
// graph-capture-legal (no sync, no allocation).
// ---------------------------------------------------------------------------
extern "C" void kernel_launch(void* const* d_in, const int* in_sizes, int n_in,
                              void* d_out, int out_size)
{
    const float* x0  = (const float*)d_in[0];
    // d_in[1] = x1 (unused)
    const void*  ei  = d_in[2];
    const float* W1  = (const float*)d_in[3];
    const float* b1  = (const float*)d_in[4];
    const float* W2  = (const float*)d_in[5];
    const float* b2  = (const float*)d_in[6];
    const float* wa1 = (const float*)d_in[7];
    const float* ba1 = (const float*)d_in[8];
    const float* wa2 = (const float*)d_in[9];
    const float* ba2 = (const float*)d_in[10];
    float* out = (float*)d_out;

    cudaFuncSetAttribute(gemm_kernel,
                         cudaFuncAttributeMaxDynamicSharedMemorySize, GEMM_SMEM);

    cudaStream_t s2;
    cudaEvent_t evFork, evJoin;
    cudaStreamCreateWithFlags(&s2, cudaStreamNonBlocking);
    cudaEventCreateWithFlags(&evFork, cudaEventDisableTiming);
    cudaEventCreateWithFlags(&evJoin, cudaEventDisableTiming);

    // 0) weight split + dtype sniff + zero counters (main stream)
    prep_kernel<<<64, 256>>>(W1, W2, (const int*)ei);

    // fork: CSR build on side stream
    cudaEventRecord(evFork, 0);
    cudaStreamWaitEvent(s2, evFork, 0);
    count_kernel<<<N_EDGES / 256, 256, 0, s2>>>(ei);
    scan_blocks_kernel<<<SCAN_NB, 1024, 0, s2>>>();
    scan_tops_kernel<<<1, 128, 0, s2>>>();
    scan_fix_kernel<<<SCAN_NB, 1024, 0, s2>>>();
    scatter_kernel<<<N_EDGES / 256, 256, 0, s2>>>(ei);
    cudaEventRecord(evJoin, s2);

    // 1) GEMM on main stream (overlaps CSR build)
    gemm_kernel<<<(N_NODES + GROWS - 1) / GROWS, 256, GEMM_SMEM>>>(
        x0, b1, b2, wa1, ba1, wa2, ba2, out);

    // join, then aggregate
    cudaStreamWaitEvent(0, evJoin, 0);
    agg_kernel<<<(N_NODES * 32 + 255) / 256, 256>>>(out);
}

// round 15
// speedup vs baseline: 2.0986x; 1.0477x over previous
#include <cuda_runtime.h>
#include <cuda_bf16.h>
#include <cstdint>

#define N_NODES 100000
#define N_EDGES 1600000
#define D_IN    128
#define D_OUT   64
#define SCAN_NB 98                         // ceil(N_NODES / 1024)

// ---------------------------------------------------------------------------
// Scratch (no allocation allowed in kernel_launch)
// ---------------------------------------------------------------------------
__device__ float g_xj[(size_t)N_NODES * D_OUT];
__device__ float g_a1[N_NODES];
__device__ float g_a2[N_NODES];
__device__ int   g_idx_is_i64;          // 1 if edge_index is int64, 0 if int32
// Transposed combined weights, bf16 hi/lo split: [n=128][k=128]
__device__ uint4 g_Wthi4[128 * 128 * 2 / 16];
__device__ uint4 g_Wtlo4[128 * 128 * 2 / 16];
// CSR binning scratch
__device__ int g_cnt[N_NODES];
__device__ int g_off[N_NODES + 1];
__device__ int g_cur[N_NODES];
__device__ int g_edst[N_EDGES];
__device__ int g_bsum[SCAN_NB];
__device__ int g_boff[SCAN_NB];

// ---------------------------------------------------------------------------
// PTX wrappers
// ---------------------------------------------------------------------------
__device__ __forceinline__ void ldsm_x4(uint32_t* r, uint32_t addr) {
    asm volatile("ldmatrix.sync.aligned.m8n8.x4.shared.b16 {%0,%1,%2,%3}, [%4];"
                 : "=r"(r[0]), "=r"(r[1]), "=r"(r[2]), "=r"(r[3]) : "r"(addr));
}
__device__ __forceinline__ void mma_bf16(float* d, const uint32_t* a, const uint32_t* b) {
    asm volatile("mma.sync.aligned.m16n8k16.row.col.f32.bf16.bf16.f32 "
                 "{%0,%1,%2,%3}, {%4,%5,%6,%7}, {%8,%9}, {%0,%1,%2,%3};"
                 : "+f"(d[0]), "+f"(d[1]), "+f"(d[2]), "+f"(d[3])
                 : "r"(a[0]), "r"(a[1]), "r"(a[2]), "r"(a[3]),
                   "r"(b[0]), "r"(b[1]));
}
__device__ __forceinline__ int load_src(const void* ei, int e, int is64) {
    return is64 ? (int)__ldg(&((const long long*)ei)[e])
                : __ldg(&((const int*)ei)[e]);
}
__device__ __forceinline__ int load_dst(const void* ei, int e, int is64) {
    return is64 ? (int)__ldg(&((const long long*)ei)[N_EDGES + e])
                : __ldg(&((const int*)ei)[N_EDGES + e]);
}

// ---------------------------------------------------------------------------
// Kernel 0 (prep): weight transpose + bf16 hi/lo split, edge-dtype sniff,
// and zero the per-node edge counters.
// ---------------------------------------------------------------------------
__global__ __launch_bounds__(256) void prep_kernel(
    const float* __restrict__ W1, const float* __restrict__ W2,
    const int* __restrict__ ei_words)
{
    const int idx = blockIdx.x * 256 + threadIdx.x;   // 64 blocks -> 16384
    const int n = idx >> 7, k = idx & 127;
    float w = (n < 64) ? W1[k * 64 + n] : W2[k * 64 + (n - 64)];
    __nv_bfloat16 hi = __float2bfloat16(w);
    __nv_bfloat16 lo = __float2bfloat16(w - __bfloat162float(hi));
    ((__nv_bfloat16*)g_Wthi4)[idx] = hi;
    ((__nv_bfloat16*)g_Wtlo4)[idx] = lo;

    for (int i = idx; i < N_NODES; i += 64 * 256) g_cnt[i] = 0;

    if (blockIdx.x == 0 && threadIdx.x == 0) {
        int odd_zero = 1;
        for (int i = 1; i < 32; i += 2)
            if (ei_words[i] != 0) odd_zero = 0;
        g_idx_is_i64 = odd_zero;
    }
}

// ---------------------------------------------------------------------------
// Kernel 1: tensor-core dual GEMM (bf16 hi/lo split) + fused epilogue.
// (unchanged)
// ---------------------------------------------------------------------------
#define GROWS 64
#define LDS_STRIDE 136
#define A_TILE (GROWS * LDS_STRIDE)
#define B_TILE (128 * LDS_STRIDE)
#define GEMM_SMEM ((2 * A_TILE + 2 * B_TILE) * 2 + 2 * 128 * 4)

__global__ __launch_bounds__(256) void gemm_kernel(
    const float* __restrict__ x0,
    const float* __restrict__ b1, const float* __restrict__ b2,
    const float* __restrict__ wa1, const float* __restrict__ ba1,
    const float* __restrict__ wa2, const float* __restrict__ ba2,
    float* __restrict__ out)
{
    extern __shared__ char smem[];
    __nv_bfloat16* sAhi = (__nv_bfloat16*)smem;
    __nv_bfloat16* sAlo = sAhi + A_TILE;
    __nv_bfloat16* sBhi = sAlo + A_TILE;
    __nv_bfloat16* sBlo = sBhi + B_TILE;
    float* sBias = (float*)(sBlo + B_TILE);
    float* sWa   = sBias + 128;

    const int tid  = threadIdx.x;
    const int row0 = blockIdx.x * GROWS;

    if (tid < 128) {
        sBias[tid] = (tid < 64) ? b1[tid] : b2[tid - 64];
        sWa[tid]   = (tid < 64) ? wa1[tid] : wa2[tid - 64];
    }
    for (int i = tid; i < 2048; i += 256) {
        int n = i >> 4, k0 = (i & 15) * 8;
        *(uint4*)(sBhi + n * LDS_STRIDE + k0) = g_Wthi4[i];
        *(uint4*)(sBlo + n * LDS_STRIDE + k0) = g_Wtlo4[i];
    }
    for (int i = tid; i < GROWS * (D_IN / 4); i += 256) {
        int r = i >> 5, c = (i & 31) * 4;
        int row = row0 + r;
        float4 v = make_float4(0.f, 0.f, 0.f, 0.f);
        if (row < N_NODES)
            v = *(const float4*)(x0 + (size_t)row * D_IN + c);
        __nv_bfloat162 h01 = __floats2bfloat162_rn(v.x, v.y);
        __nv_bfloat162 h23 = __floats2bfloat162_rn(v.z, v.w);
        float2 f01 = __bfloat1622float2(h01);
        float2 f23 = __bfloat1622float2(h23);
        __nv_bfloat162 l01 = __floats2bfloat162_rn(v.x - f01.x, v.y - f01.y);
        __nv_bfloat162 l23 = __floats2bfloat162_rn(v.z - f23.x, v.w - f23.y);
        __nv_bfloat162* ph = (__nv_bfloat162*)(sAhi + r * LDS_STRIDE + c);
        __nv_bfloat162* pl = (__nv_bfloat162*)(sAlo + r * LDS_STRIDE + c);
        ph[0] = h01; ph[1] = h23;
        pl[0] = l01; pl[1] = l23;
    }
    __syncthreads();

    const int w    = tid >> 5;
    const int lane = tid & 31;
    const int m0   = (w >> 1) * 16;
    const int wn   = w & 1;
    const int n0   = wn * 64;

    const uint32_t aAhi = (uint32_t)__cvta_generic_to_shared(sAhi);
    const uint32_t aAlo = (uint32_t)__cvta_generic_to_shared(sAlo);
    const uint32_t aBhi = (uint32_t)__cvta_generic_to_shared(sBhi);
    const uint32_t aBlo = (uint32_t)__cvta_generic_to_shared(sBlo);

    float acc[8][4];
#pragma unroll
    for (int nt = 0; nt < 8; nt++)
#pragma unroll
        for (int q = 0; q < 4; q++) acc[nt][q] = 0.f;

    const uint32_t a_row = m0 + (lane & 15);
    const uint32_t a_kof = (lane >> 4) * 8;
    const uint32_t b_row = (lane & 7) + ((lane >> 4) << 3);
    const uint32_t b_kof = ((lane >> 3) & 1) * 8;

#pragma unroll
    for (int kk = 0; kk < 8; kk++) {
        const uint32_t k0 = kk * 16;
        uint32_t ahi[4], alo[4];
        {
            uint32_t off = (a_row * LDS_STRIDE + k0 + a_kof) * 2;
            ldsm_x4(ahi, aAhi + off);
            ldsm_x4(alo, aAlo + off);
        }
#pragma unroll
        for (int ntp = 0; ntp < 4; ntp++) {
            uint32_t off = ((n0 + ntp * 16 + b_row) * LDS_STRIDE + k0 + b_kof) * 2;
            uint32_t bhi[4], blo[4];
            ldsm_x4(bhi, aBhi + off);
            ldsm_x4(blo, aBlo + off);
            mma_bf16(acc[ntp * 2 + 0], ahi, bhi + 0);
            mma_bf16(acc[ntp * 2 + 0], ahi, blo + 0);
            mma_bf16(acc[ntp * 2 + 0], alo, bhi + 0);
            mma_bf16(acc[ntp * 2 + 1], ahi, bhi + 2);
            mma_bf16(acc[ntp * 2 + 1], ahi, blo + 2);
            mma_bf16(acc[ntp * 2 + 1], alo, bhi + 2);
        }
    }

    float* basep = wn ? g_xj : out;
    const float ba = __ldg(wn ? ba2 : ba1);
    float p0 = 0.f, p1 = 0.f;
    const int rA = row0 + m0 + (lane >> 2);

#pragma unroll
    for (int nt = 0; nt < 8; nt++) {
        const int cg = n0 + nt * 8 + (lane & 3) * 2;
        const int cs = cg - n0;
        const float bb0 = sBias[cg],  bb1 = sBias[cg + 1];
        const float wv0 = sWa[cg],    wv1 = sWa[cg + 1];
        float v0 = fmaxf(acc[nt][0] + bb0, 0.f);
        float v1 = fmaxf(acc[nt][1] + bb1, 0.f);
        float v2 = fmaxf(acc[nt][2] + bb0, 0.f);
        float v3 = fmaxf(acc[nt][3] + bb1, 0.f);
        if (rA < N_NODES)
            *(float2*)(basep + (size_t)rA * D_OUT + cs) = make_float2(v0, v1);
        if (rA + 8 < N_NODES)
            *(float2*)(basep + (size_t)(rA + 8) * D_OUT + cs) = make_float2(v2, v3);
        p0 += v0 * wv0 + v1 * wv1;
        p1 += v2 * wv0 + v3 * wv1;
    }

    float* ga = wn ? g_a2 : g_a1;
#pragma unroll
    for (int h = 0; h < 2; h++) {
        float s = h ? p1 : p0;
        s += __shfl_xor_sync(0xFFFFFFFFu, s, 1);
        s += __shfl_xor_sync(0xFFFFFFFFu, s, 2);
        const int row = row0 + m0 + h * 8 + (lane >> 2);
        if ((lane & 3) == 0 && row < N_NODES)
            ga[row] = s + ba;
    }
}

// ---------------------------------------------------------------------------
// Kernel 2: count edges per src
// ---------------------------------------------------------------------------
__global__ __launch_bounds__(256) void count_kernel(const void* __restrict__ ei)
{
    const int e = blockIdx.x * 256 + threadIdx.x;   // 6250 blocks, exact
    const int s = load_src(ei, e, g_idx_is_i64);
    atomicAdd(&g_cnt[s], 1);
}

// ---------------------------------------------------------------------------
// Kernels 3a/3b/3c: parallel exclusive scan of g_cnt -> g_off/g_cur.
// ---------------------------------------------------------------------------
__global__ __launch_bounds__(1024) void scan_blocks_kernel()
{
    __shared__ int ws[32];
    const int i    = blockIdx.x * 1024 + threadIdx.x;
    const int lane = threadIdx.x & 31;
    const int wid  = threadIdx.x >> 5;

    const int c = (i < N_NODES) ? g_cnt[i] : 0;
    int v = c;
#pragma unroll
    for (int off = 1; off < 32; off <<= 1) {
        int t = __shfl_up_sync(0xFFFFFFFFu, v, off);
        if (lane >= off) v += t;
    }
    if (lane == 31) ws[wid] = v;
    __syncthreads();
    if (wid == 0) {
        int s = ws[lane];
#pragma unroll
        for (int off = 1; off < 32; off <<= 1) {
            int t = __shfl_up_sync(0xFFFFFFFFu, s, off);
            if (lane >= off) s += t;
        }
        ws[lane] = s;
    }
    __syncthreads();
    const int excl = v - c + (wid > 0 ? ws[wid - 1] : 0);
    if (i < N_NODES) g_off[i] = excl;                // block-local for now
    if (threadIdx.x == 1023) g_bsum[blockIdx.x] = excl + c;
}

__global__ __launch_bounds__(128) void scan_tops_kernel()
{
    __shared__ int sh[SCAN_NB];
    const int t = threadIdx.x;
    if (t < SCAN_NB) sh[t] = g_bsum[t];
    __syncthreads();
    if (t == 0) {                        // 98 elems: serial in smem is ~free
        int run = 0;
        for (int i = 0; i < SCAN_NB; i++) {
            int c = sh[i];
            g_boff[i] = run;
            run += c;
        }
    }
}

__global__ __launch_bounds__(1024) void scan_fix_kernel()
{
    const int i = blockIdx.x * 1024 + threadIdx.x;
    if (i < N_NODES) {
        const int o = g_off[i] + g_boff[blockIdx.x];
        g_off[i] = o;
        g_cur[i] = o;
    }
    if (i == 0) g_off[N_NODES] = N_EDGES;   // all edges counted by construction
}

// ---------------------------------------------------------------------------
// Kernel 4: scatter dst indices into CSR order
// ---------------------------------------------------------------------------
__global__ __launch_bounds__(256) void scatter_kernel(const void* __restrict__ ei)
{
    const int e = blockIdx.x * 256 + threadIdx.x;   // 6250 blocks, exact
    const int is64 = g_idx_is_i64;
    const int s = load_src(ei, e, is64);
    const int d = load_dst(ei, e, is64);
    const int pos = atomicAdd(&g_cur[s], 1);
    g_edst[pos] = d;
}

// ---------------------------------------------------------------------------
// Kernel 5: per-node aggregation (no atomics).
// One HALF-WARP per node (16 lanes hold the full 64-col row); 2-edge
// unrolled loop -> 2 outstanding gathers per half-warp (4 per warp).
// No cross-half reduce. out[n] = x0_i[n] + sum att * x0_j[d].
// ---------------------------------------------------------------------------
__global__ __launch_bounds__(256) void agg_kernel(float* __restrict__ out)
{
    const int hw = (blockIdx.x * 256 + threadIdx.x) >> 4;   // node id
    if (hw >= N_NODES) return;
    const int l = threadIdx.x & 15;

    const int beg = __ldg(&g_off[hw]);
    const int end = __ldg(&g_off[hw + 1]);
    const float a1s = __ldg(&g_a1[hw]);

    float4 acc = make_float4(0.f, 0.f, 0.f, 0.f);

    for (int i = beg; i < end; i += 2) {
        const int d0 = __ldg(&g_edst[i]);
        const int d1 = (i + 1 < end) ? __ldg(&g_edst[i + 1]) : -1;

        const float z0 = a1s + __ldg(&g_a2[d0]);
        float4 v0 = __ldg((const float4*)(g_xj + (size_t)d0 * D_OUT + l * 4));
        const float att0 = 1.f / (1.f + __expf(-z0));
        acc.x += att0 * v0.x; acc.y += att0 * v0.y;
        acc.z += att0 * v0.z; acc.w += att0 * v0.w;

        if (d1 >= 0) {
            const float z1 = a1s + __ldg(&g_a2[d1]);
            float4 v1 = __ldg((const float4*)(g_xj + (size_t)d1 * D_OUT + l * 4));
            const float att1 = 1.f / (1.f + __expf(-z1));
            acc.x += att1 * v1.x; acc.y += att1 * v1.y;
            acc.z += att1 * v1.z; acc.w += att1 * v1.w;
        }
    }

    float4* p = (float4*)(out + (size_t)hw * D_OUT + l * 4);
    float4 o = *p;                                   // x0_i
    o.x += acc.x; o.y += acc.y; o.z += acc.z; o.w += acc.w;
    *p = o;
}

// ---------------------------------------------------------------------------
// Launch: fork-join so the CSR build (edge-index only) overlaps the GEMM.
//   main:  prep ─┬─ gemm ──────────────┬─ agg
//   side:        └ count→scan*3→scatter┘
// ---------------------------------------------------------------------------
extern "C" void kernel_launch(void* const* d_in, const int* in_sizes, int n_in,
                              void* d_out, int out_size)
{
    const float* x0  = (const float*)d_in[0];
    // d_in[1] = x1 (unused)
    const void*  ei  = d_in[2];
    const float* W1  = (const float*)d_in[3];
    const float* b1  = (const float*)d_in[4];
    const float* W2  = (const float*)d_in[5];
    const float* b2  = (const float*)d_in[6];
    const float* wa1 = (const float*)d_in[7];
    const float* ba1 = (const float*)d_in[8];
    const float* wa2 = (const float*)d_in[9];
    const float* ba2 = (const float*)d_in[10];
    float* out = (float*)d_out;

    cudaFuncSetAttribute(gemm_kernel,
                         cudaFuncAttributeMaxDynamicSharedMemorySize, GEMM_SMEM);

    cudaStream_t s2;
    cudaEvent_t evFork, evJoin;
    cudaStreamCreateWithFlags(&s2, cudaStreamNonBlocking);
    cudaEventCreateWithFlags(&evFork, cudaEventDisableTiming);
    cudaEventCreateWithFlags(&evJoin, cudaEventDisableTiming);

    // 0) weight split + dtype sniff + zero counters (main stream)
    prep_kernel<<<64, 256>>>(W1, W2, (const int*)ei);

    // fork: CSR build on side stream
    cudaEventRecord(evFork, 0);
    cudaStreamWaitEvent(s2, evFork, 0);
    count_kernel<<<N_EDGES / 256, 256, 0, s2>>>(ei);
    scan_blocks_kernel<<<SCAN_NB, 1024, 0, s2>>>();
    scan_tops_kernel<<<1, 128, 0, s2>>>();
    scan_fix_kernel<<<SCAN_NB, 1024, 0, s2>>>();
    scatter_kernel<<<N_EDGES / 256, 256, 0, s2>>>(ei);
    cudaEventRecord(evJoin, s2);

    // 1) GEMM on main stream (overlaps CSR build)
    gemm_kernel<<<(N_NODES + GROWS - 1) / GROWS, 256, GEMM_SMEM>>>(
        x0, b1, b2, wa1, ba1, wa2, ba2, out);

    // join, then aggregate
    cudaStreamWaitEvent(0, evJoin, 0);
    agg_kernel<<<(N_NODES * 16 + 255) / 256, 256>>>(out);
}